// round 13
// baseline (speedup 1.0000x reference)
#include <cuda_runtime.h>
#include <cuda_fp16.h>
#include <math.h>
#include <stdint.h>

#define B_SZ 4096
#define T_SZ 80
#define E_SZ 100
#define U_SZ 1024
#define V_SZ 10000

// CTA tile 128x128, BK=64, 128 threads (4 warps, each 64x64), 2-stage ring
// 3 CTAs resident per SM (smem 3x65.5KB = 197KB, regs capped at 170)
#define BM 128
#define BN 128
#define BK 64
#define A_PL 0
#define B_PL 16384
#define STAGE 32768
#define NBUF 2
#define SMEM_DYN (NBUF * STAGE + 1024)

// ---------------------------------------------------------------------------
// Scratch (__device__ globals)
// ---------------------------------------------------------------------------
__device__ __align__(16) __half g_wt[3][U_SZ * U_SZ];  // Wh0, Wx1, Wh1 fp16 [n][k]
__device__ __align__(16) __half g_xw0[V_SZ * U_SZ];    // fp16(emb@Wx0 + b0)
__device__ __align__(16) __half g_h[4][B_SZ * U_SZ];   // h0 ping/pong, h1 ping/pong

// ---------------------------------------------------------------------------
// helpers
// ---------------------------------------------------------------------------
__device__ __forceinline__ uint32_t smem_u32(const void* p) {
    uint32_t a;
    asm("{ .reg .u64 t; cvta.to.shared.u64 t, %1; cvt.u32.u64 %0, t; }"
        : "=r"(a) : "l"(p));
    return a;
}
__device__ __forceinline__ uint32_t swz128(uint32_t off) {
    return off ^ ((off >> 3) & 0x70);
}
__device__ __forceinline__ void cpa16(uint32_t dst, const void* src) {
    asm volatile("cp.async.cg.shared.global [%0], [%1], 16;" :: "r"(dst), "l"(src));
}
__device__ __forceinline__ void ldsm4(uint32_t* r, uint32_t addr) {
    asm volatile("ldmatrix.sync.aligned.m8n8.x4.shared.b16 {%0,%1,%2,%3}, [%4];"
                 : "=r"(r[0]), "=r"(r[1]), "=r"(r[2]), "=r"(r[3]) : "r"(addr));
}
__device__ __forceinline__ void mma16816(float* c, const uint32_t* a, const uint32_t* b) {
    asm volatile(
        "mma.sync.aligned.m16n8k16.row.col.f32.f16.f16.f32 "
        "{%0,%1,%2,%3}, {%4,%5,%6,%7}, {%8,%9}, {%0,%1,%2,%3};"
        : "+f"(c[0]), "+f"(c[1]), "+f"(c[2]), "+f"(c[3])
        : "r"(a[0]), "r"(a[1]), "r"(a[2]), "r"(a[3]), "r"(b[0]), "r"(b[1]));
}

// ---------------------------------------------------------------------------
// Combined step kernel (z=0: layer1 LONG jobs first for LPT; z=1: layer0).
//   z==1 (if do0): h0w = tanh(h0r @ Wh0 + xw0[inputs[:,t0]])      (layer 0, t0)
//   z==0 (if do1): h1w = tanh(h0r @ Wx1 + h1r @ Wh1 + b1)         (layer 1, t0-1)
// ---------------------------------------------------------------------------
__global__ void __launch_bounds__(128, 3)
rnn_pair_kernel(const __half* __restrict__ h0r, __half* __restrict__ h0w,
                const __half* __restrict__ h1r, __half* __restrict__ h1w,
                const __half* __restrict__ Wh0, const __half* __restrict__ Wx1,
                const __half* __restrict__ Wh1,
                const float* __restrict__ b1,
                const __half* __restrict__ xw0,
                const int* __restrict__ inputs, int t0,
                int do0, int do1) {
    const int z = blockIdx.z;
    if (z == 0) { if (!do1) return; } else { if (!do0) return; }

    extern __shared__ char dsm[];
    const uint32_t tile = (smem_u32(dsm) + 1023u) & ~1023u;

    const int tid = threadIdx.x;
    const int wid = tid >> 5;
    const int lane = tid & 31;
    const int m0 = blockIdx.y * BM;
    const int n0 = blockIdx.x * BN;

    const int mW = (wid & 1) * 64;     // 2 warps along M
    const int nW = (wid >> 1) * 64;    // 2 warps along N

    // segments (z=0 -> layer1: 2 segs; z=1 -> layer0: 1 seg)
    const __half* Ap[2];
    const __half* Wp[2];
    int nseg;
    if (z == 1) { Ap[0] = h0r; Wp[0] = Wh0; Ap[1] = nullptr; Wp[1] = nullptr; nseg = 1; }
    else        { Ap[0] = h0r; Wp[0] = Wx1; Ap[1] = h1r;    Wp[1] = Wh1;     nseg = 2; }

    const int NST = nseg * (U_SZ / BK);    // 16 or 32 stages

    auto load_stage = [&](int s) {
        const int seg = s >> 4;
        const int k0 = (s & 15) * BK;
        const uint32_t bb = tile + (uint32_t)(s & 1) * STAGE;
        const __half* ap = Ap[seg];
        const __half* wp = Wp[seg];
#pragma unroll
        for (int i = 0; i < 8; ++i) {
            int c = tid + i * 128;
            int r = c >> 3;
            int c16 = (c & 7) * 16;
            uint32_t doff = swz128((uint32_t)(r * 128 + c16));
            size_t ga = (size_t)(m0 + r) * U_SZ + k0 + (c16 >> 1);
            size_t gb = (size_t)(n0 + r) * U_SZ + k0 + (c16 >> 1);
            cpa16(bb + A_PL + doff, ap + ga);
            cpa16(bb + B_PL + doff, wp + gb);
        }
        asm volatile("cp.async.commit_group;" ::: "memory");
    };

    float acc[4][8][4];
#pragma unroll
    for (int i = 0; i < 4; ++i)
#pragma unroll
        for (int j = 0; j < 8; ++j)
#pragma unroll
            for (int q = 0; q < 4; ++q) acc[i][j][q] = 0.0f;

    // per-warp ldmatrix source offsets
    const int a_row = mW + (lane & 15);
    const int a_cg  = (lane >> 4) * 16;
    const int b_q   = lane >> 3;
    const int b_row = nW + ((b_q >> 1) * 8) + (lane & 7);
    const int b_cg  = (b_q & 1) * 16;

    load_stage(0);

    for (int s = 0; s < NST; ++s) {
        if (s + 1 < NST) {
            load_stage(s + 1);
            asm volatile("cp.async.wait_group 1;" ::: "memory");
        } else {
            asm volatile("cp.async.wait_group 0;" ::: "memory");
        }
        __syncthreads();

        const uint32_t bb = tile + (uint32_t)(s & 1) * STAGE;
#pragma unroll
        for (int ks = 0; ks < 4; ++ks) {
            uint32_t af[4][4], bf[8][2];
#pragma unroll
            for (int i = 0; i < 4; ++i) {
                uint32_t off = swz128((uint32_t)((a_row + i * 16) * 128 + ks * 32 + a_cg));
                ldsm4(af[i], bb + A_PL + off);
            }
#pragma unroll
            for (int j2 = 0; j2 < 4; ++j2) {
                uint32_t off = swz128((uint32_t)((b_row + j2 * 16) * 128 + ks * 32 + b_cg));
                uint32_t r[4];
                ldsm4(r, bb + B_PL + off);
                bf[j2 * 2][0] = r[0]; bf[j2 * 2][1] = r[1];
                bf[j2 * 2 + 1][0] = r[2]; bf[j2 * 2 + 1][1] = r[3];
            }
#pragma unroll
            for (int i = 0; i < 4; ++i)
#pragma unroll
                for (int j = 0; j < 8; ++j)
                    mma16816(acc[i][j], af[i], bf[j]);
        }
        __syncthreads();   // compute(s) done before load(s+2) overwrites buffer s&1
    }

    // ---- epilogue ----
    __half* outp = (z == 1) ? h0w : h1w;
    const int gp = lane >> 2;
    const int t4 = lane & 3;
#pragma unroll
    for (int i = 0; i < 4; ++i) {
#pragma unroll
        for (int rh = 0; rh < 2; ++rh) {
            const int m = m0 + mW + i * 16 + gp + rh * 8;
            const __half* xr = nullptr;
            if (z == 1) xr = xw0 + (size_t)inputs[(size_t)m * T_SZ + t0] * U_SZ;
#pragma unroll
            for (int j = 0; j < 8; ++j) {
                const int col = n0 + nW + j * 8 + t4 * 2;
                float v0 = acc[i][j][rh * 2 + 0];
                float v1 = acc[i][j][rh * 2 + 1];
                if (z == 1) {
                    __half2 x2 = *(const __half2*)(xr + col);
                    v0 += __half2float(x2.x); v1 += __half2float(x2.y);
                } else {
                    v0 += b1[col]; v1 += b1[col + 1];
                }
                __half h0 = __float2half_rn(tanhf(v0));
                __half h1 = __float2half_rn(tanhf(v1));
                uint32_t p = (uint32_t)__half_as_ushort(h0) |
                             ((uint32_t)__half_as_ushort(h1) << 16);
                *(uint32_t*)(outp + (size_t)m * U_SZ + col) = p;
            }
        }
    }
}

// ---------------------------------------------------------------------------
// Prep: transpose the three recurrent weight matrices to fp16 [n][k]
// ---------------------------------------------------------------------------
__global__ void __launch_bounds__(256)
transpose_split_kernel(const float* __restrict__ W0, const float* __restrict__ W1,
                       const float* __restrict__ W2) {
    __shared__ float tilebuf[32][33];
    const int z = blockIdx.z;
    const float* W = (z == 0) ? W0 : ((z == 1) ? W1 : W2);
    __half* Th = g_wt[z];
    const int tx = threadIdx.x & 31, ty = threadIdx.x >> 5;
    const int x = blockIdx.x * 32 + tx;
    const int y0 = blockIdx.y * 32;
#pragma unroll
    for (int j = 0; j < 32; j += 8)
        tilebuf[ty + j][tx] = W[(size_t)(y0 + ty + j) * U_SZ + x];
    __syncthreads();
    const int x2 = blockIdx.y * 32 + tx;
#pragma unroll
    for (int j = 0; j < 32; j += 8) {
        int n = blockIdx.x * 32 + ty + j;
        Th[(size_t)n * U_SZ + x2] = __float2half_rn(tilebuf[tx][ty + j]);
    }
}

// ---------------------------------------------------------------------------
// Prep: xw0[v][n] = fp16( b0[n] + sum_k emb[v,k] * Wx0[k,n] )
// ---------------------------------------------------------------------------
__global__ void __launch_bounds__(256)
xw0_kernel(const float* __restrict__ emb, const float* __restrict__ Wx0,
           const float* __restrict__ b0, __half* __restrict__ xw0) {
    __shared__ float es[16][104];
    const int v0 = blockIdx.y * 16;
    const int n = blockIdx.x * 256 + threadIdx.x;
    for (int i = threadIdx.x; i < 16 * E_SZ; i += 256) {
        int r = i / E_SZ, c = i % E_SZ;
        es[r][c] = emb[(size_t)(v0 + r) * E_SZ + c];
    }
    __syncthreads();
    float acc[16];
    float bv = b0[n];
#pragma unroll
    for (int i = 0; i < 16; ++i) acc[i] = bv;
    for (int k = 0; k < E_SZ; ++k) {
        float w = Wx0[(size_t)k * U_SZ + n];
#pragma unroll
        for (int i = 0; i < 16; ++i) acc[i] = fmaf(es[i][k], w, acc[i]);
    }
#pragma unroll
    for (int i = 0; i < 16; ++i)
        xw0[(size_t)(v0 + i) * U_SZ + n] = __float2half_rn(acc[i]);
}

// ---------------------------------------------------------------------------
__global__ void zero2_kernel(__half* a, __half* b) {
    size_t i = (size_t)blockIdx.x * blockDim.x + threadIdx.x;
    uint4 z = make_uint4(0, 0, 0, 0);
    ((uint4*)a)[i] = z; ((uint4*)b)[i] = z;
}

// ---------------------------------------------------------------------------
__global__ void __launch_bounds__(256)
final_kernel(const __half* __restrict__ h1, const float* __restrict__ Wfc,
             const float* __restrict__ bfc, float* __restrict__ out) {
    int warp = (blockIdx.x * blockDim.x + threadIdx.x) >> 5;
    int lane = threadIdx.x & 31;
    if (warp >= B_SZ) return;
    float s = 0.0f;
#pragma unroll
    for (int u = lane; u < U_SZ; u += 32)
        s = fmaf(__half2float(h1[(size_t)warp * U_SZ + u]), Wfc[u], s);
#pragma unroll
    for (int o = 16; o > 0; o >>= 1) s += __shfl_xor_sync(0xffffffffu, s, o);
    if (lane == 0) {
        float z = s + bfc[0];
        out[warp] = 1.0f / (1.0f + expf(-z));
    }
}

// ---------------------------------------------------------------------------
extern "C" void kernel_launch(void* const* d_in, const int* in_sizes, int n_in,
                              void* d_out, int out_size) {
    const int*   inputs = (const int*)  d_in[0];
    const float* emb    = (const float*)d_in[1];
    const float* Wx0    = (const float*)d_in[2];
    const float* Wh0    = (const float*)d_in[3];
    const float* b0     = (const float*)d_in[4];
    const float* Wx1    = (const float*)d_in[5];
    const float* Wh1    = (const float*)d_in[6];
    const float* b1     = (const float*)d_in[7];
    const float* Wfc    = (const float*)d_in[8];
    const float* bfc    = (const float*)d_in[9];
    float* out = (float*)d_out;

    cudaFuncSetAttribute(rnn_pair_kernel,
                         cudaFuncAttributeMaxDynamicSharedMemorySize, SMEM_DYN);

    __half *wt, *h, *xw0;
    cudaGetSymbolAddress((void**)&wt, g_wt);
    cudaGetSymbolAddress((void**)&xw0, g_xw0);
    cudaGetSymbolAddress((void**)&h, g_h);

    const size_t WS = (size_t)U_SZ * U_SZ;
    __half* Wh0q = wt + 0 * WS;
    __half* Wx1q = wt + 1 * WS;
    __half* Wh1q = wt + 2 * WS;

    const size_t HS = (size_t)B_SZ * U_SZ;
    __half* h0[2] = {h + 0 * HS, h + 1 * HS};
    __half* h1[2] = {h + 2 * HS, h + 3 * HS};

    transpose_split_kernel<<<dim3(32, 32, 3), 256>>>(Wh0, Wx1, Wh1);
    xw0_kernel<<<dim3(4, V_SZ / 16), 256>>>(emb, Wx0, b0, xw0);
    zero2_kernel<<<(unsigned)(HS / 8 / 256), 256>>>(h0[0], h1[0]);

    dim3 grid(U_SZ / BN, B_SZ / BM, 2);   // (8, 32, 2); z=0 = layer1 (long, LPT first)

    // launch t: z=1 computes layer0(t) [if t<80]; z=0 computes layer1(t-1) [if t>0]
    for (int t = 0; t <= T_SZ; ++t) {
        const int p = t & 1;
        rnn_pair_kernel<<<grid, 128, SMEM_DYN>>>(
            h0[p], h0[p ^ 1],
            h1[p ^ 1], h1[p],
            Wh0q, Wx1q, Wh1q,
            b1, xw0, inputs, t,
            (t < T_SZ) ? 1 : 0, (t > 0) ? 1 : 0);
    }

    // layer1(79) ran at t=80 (p=0), wrote h1[0]
    final_kernel<<<B_SZ / 8, 256>>>(h1[0], Wfc, bfc, out);
}

// round 14
// speedup vs baseline: 1.2457x; 1.2457x over previous
#include <cuda_runtime.h>
#include <cuda_fp16.h>
#include <math.h>
#include <stdint.h>

#define B_SZ 4096
#define T_SZ 80
#define E_SZ 100
#define U_SZ 1024
#define V_SZ 10000

// CTA tile 128x128, BK=32 per stage, 128 threads (4 warps, each 64x64)
// 6-deep stage ring (96KB), one CTA barrier per 3 stages, 2 CTAs/SM.
#define BM 128
#define BN 128
#define BK 32
#define A_PL 0
#define B_PL 8192
#define STAGE 16384
#define NBUF 6
#define SMEM_DYN (NBUF * STAGE + 1024)

// ---------------------------------------------------------------------------
// Scratch (__device__ globals)
// ---------------------------------------------------------------------------
__device__ __align__(16) __half g_wt[3][U_SZ * U_SZ];  // Wh0, Wx1, Wh1 fp16 [n][k]
__device__ __align__(16) __half g_xw0[V_SZ * U_SZ];    // fp16(emb@Wx0 + b0)
__device__ __align__(16) __half g_h[4][B_SZ * U_SZ];   // h0 ping/pong, h1 ping/pong

// ---------------------------------------------------------------------------
// helpers
// ---------------------------------------------------------------------------
__device__ __forceinline__ uint32_t smem_u32(const void* p) {
    uint32_t a;
    asm("{ .reg .u64 t; cvta.to.shared.u64 t, %1; cvt.u32.u64 %0, t; }"
        : "=r"(a) : "l"(p));
    return a;
}
__device__ __forceinline__ uint32_t swz128(uint32_t off) {
    return off ^ ((off >> 3) & 0x70);
}
// physical offset of (logical row r, byte kb within 64B row-half) in a plane:
// two logical 64B halves packed per 128B physical row; swizzled.
__device__ __forceinline__ uint32_t plane_off(int r, int kb) {
    return swz128((uint32_t)((r & 63) * 128 + ((r >> 6) << 6) + kb));
}
__device__ __forceinline__ void cpa16(uint32_t dst, const void* src) {
    asm volatile("cp.async.cg.shared.global [%0], [%1], 16;" :: "r"(dst), "l"(src));
}
__device__ __forceinline__ void ldsm4(uint32_t* r, uint32_t addr) {
    asm volatile("ldmatrix.sync.aligned.m8n8.x4.shared.b16 {%0,%1,%2,%3}, [%4];"
                 : "=r"(r[0]), "=r"(r[1]), "=r"(r[2]), "=r"(r[3]) : "r"(addr));
}
__device__ __forceinline__ void mma16816(float* c, const uint32_t* a, const uint32_t* b) {
    asm volatile(
        "mma.sync.aligned.m16n8k16.row.col.f32.f16.f16.f32 "
        "{%0,%1,%2,%3}, {%4,%5,%6,%7}, {%8,%9}, {%0,%1,%2,%3};"
        : "+f"(c[0]), "+f"(c[1]), "+f"(c[2]), "+f"(c[3])
        : "r"(a[0]), "r"(a[1]), "r"(a[2]), "r"(a[3]), "r"(b[0]), "r"(b[1]));
}

// ---------------------------------------------------------------------------
// Combined step kernel.
//   z==0: layer0: h0w = tanh(h0r @ Wh0 + xw0[inputs[:,t0]])    NST=nst_l0
//         (nst_l0==0 -> epilogue-only: tanh(xw0); nst_l0<0 -> off)
//   z==1: layer1: h1w = tanh(h0r @ Wx1 [+ h1r @ Wh1] + b1)     NST=nst_l1
//         (nst_l1==0 -> off; 32 -> Wx1 only; 64 -> both segments)
// ---------------------------------------------------------------------------
__global__ void __launch_bounds__(128, 2)
rnn_pair_kernel(const __half* __restrict__ h0r, __half* __restrict__ h0w,
                const __half* __restrict__ h1r, __half* __restrict__ h1w,
                const __half* __restrict__ Wh0, const __half* __restrict__ Wx1,
                const __half* __restrict__ Wh1,
                const float* __restrict__ b1,
                const __half* __restrict__ xw0,
                const int* __restrict__ inputs, int t0,
                int nst_l0, int nst_l1) {
    const int z = blockIdx.z;
    const int NST = (z == 0) ? nst_l0 : nst_l1;
    if (NST < 0 || (z == 1 && NST == 0)) return;

    extern __shared__ char dsm[];
    const uint32_t tile = (smem_u32(dsm) + 1023u) & ~1023u;

    const int tid = threadIdx.x;
    const int wid = tid >> 5;
    const int lane = tid & 31;
    const int m0 = blockIdx.y * BM;
    const int n0 = blockIdx.x * BN;

    const int mW = (wid & 1) * 64;     // 2 warps along M
    const int nW = (wid >> 1) * 64;    // 2 warps along N

    const __half* Ap[2];
    const __half* Wp[2];
    if (z == 0) { Ap[0] = h0r; Wp[0] = Wh0; Ap[1] = nullptr; Wp[1] = nullptr; }
    else        { Ap[0] = h0r; Wp[0] = Wx1; Ap[1] = h1r;    Wp[1] = Wh1;     }

    // staging: per plane 8KB = 512 x 16B chunks; 4 chunks/thread.
    // chunk c: logical row r = c>>2, kb = (c&3)*16
    int lrow[4], lkb[4];
    uint32_t ldst[4];
#pragma unroll
    for (int i = 0; i < 4; ++i) {
        int c = tid + i * 128;
        lrow[i] = c >> 2;
        lkb[i]  = (c & 3) * 16;
        ldst[i] = plane_off(lrow[i], lkb[i]);
    }

    auto load_stage = [&](int s) {
        if (s < NST) {
            const int seg = s >> 5;             // 32 stages per K=1024 segment
            const int k0 = (s & 31) * BK;
            const uint32_t bb = tile + (uint32_t)(s % NBUF) * STAGE;
            const __half* ap = Ap[seg];
            const __half* wp = Wp[seg];
#pragma unroll
            for (int i = 0; i < 4; ++i) {
                size_t ga = (size_t)(m0 + lrow[i]) * U_SZ + k0 + (lkb[i] >> 1);
                size_t gb = (size_t)(n0 + lrow[i]) * U_SZ + k0 + (lkb[i] >> 1);
                cpa16(bb + A_PL + ldst[i], ap + ga);
                cpa16(bb + B_PL + ldst[i], wp + gb);
            }
        }
        asm volatile("cp.async.commit_group;" ::: "memory");   // uniform counting
    };

    float acc[4][8][4];
#pragma unroll
    for (int i = 0; i < 4; ++i)
#pragma unroll
        for (int j = 0; j < 8; ++j)
#pragma unroll
            for (int q = 0; q < 4; ++q) acc[i][j][q] = 0.0f;

    // per-warp ldmatrix logical coordinates
    const int a_row = mW + (lane & 15);
    const int a_cg  = (lane >> 4) * 16;
    const int b_q   = lane >> 3;
    const int b_row = nW + ((b_q >> 1) * 8) + (lane & 7);
    const int b_cg  = (b_q & 1) * 16;

    // one stage of compute: 2 k16 sub-steps from buffer s%6
    auto compute_stage = [&](int s) {
        const uint32_t bb = tile + (uint32_t)(s % NBUF) * STAGE;
#pragma unroll
        for (int ks = 0; ks < 2; ++ks) {
            uint32_t af[4][4], bf[8][2];
#pragma unroll
            for (int i = 0; i < 4; ++i)
                ldsm4(af[i], bb + A_PL + plane_off(a_row + i * 16, ks * 32 + a_cg));
#pragma unroll
            for (int j2 = 0; j2 < 4; ++j2) {
                uint32_t r[4];
                ldsm4(r, bb + B_PL + plane_off(b_row + j2 * 16, ks * 32 + b_cg));
                bf[j2 * 2][0] = r[0]; bf[j2 * 2][1] = r[1];
                bf[j2 * 2 + 1][0] = r[2]; bf[j2 * 2 + 1][1] = r[3];
            }
#pragma unroll
            for (int i = 0; i < 4; ++i)
#pragma unroll
                for (int j = 0; j < 8; ++j)
                    mma16816(acc[i][j], af[i], bf[j]);
        }
    };

    if (NST > 0) {
        load_stage(0);
        load_stage(1);
        load_stage(2);
        for (int s0 = 0; s0 < NST; s0 += 3) {
            // barrier covers completion of stages s0-3..s0-1 by ALL warps,
            // freeing buffers (s0+3..s0+5)%6 for the loads below.
            __syncthreads();
            load_stage(s0 + 3);
            load_stage(s0 + 4);
            load_stage(s0 + 5);
            asm volatile("cp.async.wait_group 5;" ::: "memory");
            compute_stage(s0);
            if (s0 + 1 < NST) {
                asm volatile("cp.async.wait_group 4;" ::: "memory");
                compute_stage(s0 + 1);
            }
            if (s0 + 2 < NST) {
                asm volatile("cp.async.wait_group 3;" ::: "memory");
                compute_stage(s0 + 2);
            }
        }
    }

    // ---- epilogue ----
    __half* outp = (z == 0) ? h0w : h1w;
    const int gp = lane >> 2;
    const int t4 = lane & 3;
#pragma unroll
    for (int i = 0; i < 4; ++i) {
#pragma unroll
        for (int rh = 0; rh < 2; ++rh) {
            const int m = m0 + mW + i * 16 + gp + rh * 8;
            const __half* xr = nullptr;
            if (z == 0) xr = xw0 + (size_t)inputs[(size_t)m * T_SZ + t0] * U_SZ;
#pragma unroll
            for (int j = 0; j < 8; ++j) {
                const int col = n0 + nW + j * 8 + t4 * 2;
                float v0 = acc[i][j][rh * 2 + 0];
                float v1 = acc[i][j][rh * 2 + 1];
                if (z == 0) {
                    __half2 x2 = *(const __half2*)(xr + col);
                    v0 += __half2float(x2.x); v1 += __half2float(x2.y);
                } else {
                    v0 += b1[col]; v1 += b1[col + 1];
                }
                __half h0 = __float2half_rn(tanhf(v0));
                __half h1 = __float2half_rn(tanhf(v1));
                uint32_t p = (uint32_t)__half_as_ushort(h0) |
                             ((uint32_t)__half_as_ushort(h1) << 16);
                *(uint32_t*)(outp + (size_t)m * U_SZ + col) = p;
            }
        }
    }
}

// ---------------------------------------------------------------------------
// Prep: transpose the three recurrent weight matrices to fp16 [n][k]
// ---------------------------------------------------------------------------
__global__ void __launch_bounds__(256)
transpose_split_kernel(const float* __restrict__ W0, const float* __restrict__ W1,
                       const float* __restrict__ W2) {
    __shared__ float tilebuf[32][33];
    const int z = blockIdx.z;
    const float* W = (z == 0) ? W0 : ((z == 1) ? W1 : W2);
    __half* Th = g_wt[z];
    const int tx = threadIdx.x & 31, ty = threadIdx.x >> 5;
    const int x = blockIdx.x * 32 + tx;
    const int y0 = blockIdx.y * 32;
#pragma unroll
    for (int j = 0; j < 32; j += 8)
        tilebuf[ty + j][tx] = W[(size_t)(y0 + ty + j) * U_SZ + x];
    __syncthreads();
    const int x2 = blockIdx.y * 32 + tx;
#pragma unroll
    for (int j = 0; j < 32; j += 8) {
        int n = blockIdx.x * 32 + ty + j;
        Th[(size_t)n * U_SZ + x2] = __float2half_rn(tilebuf[tx][ty + j]);
    }
}

// ---------------------------------------------------------------------------
// Prep: xw0[v][n] = fp16( b0[n] + sum_k emb[v,k] * Wx0[k,n] )
// ---------------------------------------------------------------------------
__global__ void __launch_bounds__(256)
xw0_kernel(const float* __restrict__ emb, const float* __restrict__ Wx0,
           const float* __restrict__ b0, __half* __restrict__ xw0) {
    __shared__ float es[16][104];
    const int v0 = blockIdx.y * 16;
    const int n = blockIdx.x * 256 + threadIdx.x;
    for (int i = threadIdx.x; i < 16 * E_SZ; i += 256) {
        int r = i / E_SZ, c = i % E_SZ;
        es[r][c] = emb[(size_t)(v0 + r) * E_SZ + c];
    }
    __syncthreads();
    float acc[16];
    float bv = b0[n];
#pragma unroll
    for (int i = 0; i < 16; ++i) acc[i] = bv;
    for (int k = 0; k < E_SZ; ++k) {
        float w = Wx0[(size_t)k * U_SZ + n];
#pragma unroll
        for (int i = 0; i < 16; ++i) acc[i] = fmaf(es[i][k], w, acc[i]);
    }
#pragma unroll
    for (int i = 0; i < 16; ++i)
        xw0[(size_t)(v0 + i) * U_SZ + n] = __float2half_rn(acc[i]);
}

// ---------------------------------------------------------------------------
__global__ void __launch_bounds__(256)
final_kernel(const __half* __restrict__ h1, const float* __restrict__ Wfc,
             const float* __restrict__ bfc, float* __restrict__ out) {
    int warp = (blockIdx.x * blockDim.x + threadIdx.x) >> 5;
    int lane = threadIdx.x & 31;
    if (warp >= B_SZ) return;
    float s = 0.0f;
#pragma unroll
    for (int u = lane; u < U_SZ; u += 32)
        s = fmaf(__half2float(h1[(size_t)warp * U_SZ + u]), Wfc[u], s);
#pragma unroll
    for (int o = 16; o > 0; o >>= 1) s += __shfl_xor_sync(0xffffffffu, s, o);
    if (lane == 0) {
        float z = s + bfc[0];
        out[warp] = 1.0f / (1.0f + expf(-z));
    }
}

// ---------------------------------------------------------------------------
extern "C" void kernel_launch(void* const* d_in, const int* in_sizes, int n_in,
                              void* d_out, int out_size) {
    const int*   inputs = (const int*)  d_in[0];
    const float* emb    = (const float*)d_in[1];
    const float* Wx0    = (const float*)d_in[2];
    const float* Wh0    = (const float*)d_in[3];
    const float* b0     = (const float*)d_in[4];
    const float* Wx1    = (const float*)d_in[5];
    const float* Wh1    = (const float*)d_in[6];
    const float* b1     = (const float*)d_in[7];
    const float* Wfc    = (const float*)d_in[8];
    const float* bfc    = (const float*)d_in[9];
    float* out = (float*)d_out;

    cudaFuncSetAttribute(rnn_pair_kernel,
                         cudaFuncAttributeMaxDynamicSharedMemorySize, SMEM_DYN);

    __half *wt, *h, *xw0;
    cudaGetSymbolAddress((void**)&wt, g_wt);
    cudaGetSymbolAddress((void**)&xw0, g_xw0);
    cudaGetSymbolAddress((void**)&h, g_h);

    const size_t WS = (size_t)U_SZ * U_SZ;
    __half* Wh0q = wt + 0 * WS;
    __half* Wx1q = wt + 1 * WS;
    __half* Wh1q = wt + 2 * WS;

    const size_t HS = (size_t)B_SZ * U_SZ;
    __half* h0[2] = {h + 0 * HS, h + 1 * HS};
    __half* h1[2] = {h + 2 * HS, h + 3 * HS};

    transpose_split_kernel<<<dim3(32, 32, 3), 256>>>(Wh0, Wx1, Wh1);
    xw0_kernel<<<dim3(4, V_SZ / 16), 256>>>(emb, Wx0, b0, xw0);
    // no zero-init needed: t=0 layer0 is epilogue-only (h0 = tanh(xw0));
    // t=1 layer1 skips the Wh1 segment (h1_prev = 0).

    dim3 grid(U_SZ / BN, B_SZ / BM, 2);   // (8, 32, 2)

    // launch t: z=0 computes layer0(t) [t<80]; z=1 computes layer1(t-1) [t>0]
    for (int t = 0; t <= T_SZ; ++t) {
        const int p = t & 1;
        const int nst_l0 = (t < T_SZ) ? ((t == 0) ? 0 : 32) : -1;
        const int nst_l1 = (t > 0) ? ((t == 1) ? 32 : 64) : 0;
        rnn_pair_kernel<<<grid, 128, SMEM_DYN>>>(
            h0[p], h0[p ^ 1],
            h1[p ^ 1], h1[p],
            Wh0q, Wx1q, Wh1q,
            b1, xw0, inputs, t,
            nst_l0, nst_l1);
    }

    // layer1(79) ran at t=80 (p=0), wrote h1[0]
    final_kernel<<<B_SZ / 8, 256>>>(h1[0], Wfc, bfc, out);
}

// round 15
// speedup vs baseline: 1.2714x; 1.0207x over previous
#include <cuda_runtime.h>
#include <cuda_fp16.h>
#include <math.h>
#include <stdint.h>

#define B_SZ 4096
#define T_SZ 80
#define E_SZ 100
#define U_SZ 1024
#define V_SZ 10000

// CTA tile 128x128, BK=32 per stage, 128 threads (4 warps, each 64x64)
// 6-deep stage ring (96KB), one CTA barrier per 3 stages, 2 CTAs/SM.
#define BM 128
#define BN 128
#define BK 32
#define A_PL 0
#define B_PL 8192
#define STAGE 16384
#define NBUF 6
#define SMEM_DYN (NBUF * STAGE + 1024)

// ---------------------------------------------------------------------------
// Scratch (__device__ globals)
// ---------------------------------------------------------------------------
__device__ __align__(16) __half g_wt[3][U_SZ * U_SZ];  // Wh0, Wx1, Wh1 fp16 [n][k]
__device__ __align__(16) __half g_xw0[V_SZ * U_SZ];    // fp16(emb@Wx0 + b0)
__device__ __align__(16) __half g_h[4][B_SZ * U_SZ];   // h0 ping/pong, h1 ping/pong

// ---------------------------------------------------------------------------
// helpers
// ---------------------------------------------------------------------------
__device__ __forceinline__ uint32_t smem_u32(const void* p) {
    uint32_t a;
    asm("{ .reg .u64 t; cvta.to.shared.u64 t, %1; cvt.u32.u64 %0, t; }"
        : "=r"(a) : "l"(p));
    return a;
}
__device__ __forceinline__ uint32_t swz128(uint32_t off) {
    return off ^ ((off >> 3) & 0x70);
}
// physical offset of (logical row r, byte kb within 64B row-half) in a plane:
// two logical 64B halves packed per 128B physical row; swizzled.
// NOTE: for kb in bits[4:6] (0/16/32/48), swz128(base+kb) == swz128(base)^kb,
// because the swizzle mask derives from bits[7:9] (row bits), untouched by kb.
__device__ __forceinline__ uint32_t plane_off(int r, int kb) {
    return swz128((uint32_t)((r & 63) * 128 + ((r >> 6) << 6) + kb));
}
__device__ __forceinline__ void cpa16(uint32_t dst, const void* src) {
    asm volatile("cp.async.cg.shared.global [%0], [%1], 16;" :: "r"(dst), "l"(src));
}
__device__ __forceinline__ void ldsm4(uint32_t* r, uint32_t addr) {
    asm volatile("ldmatrix.sync.aligned.m8n8.x4.shared.b16 {%0,%1,%2,%3}, [%4];"
                 : "=r"(r[0]), "=r"(r[1]), "=r"(r[2]), "=r"(r[3]) : "r"(addr));
}
__device__ __forceinline__ void mma16816(float* c, const uint32_t* a, const uint32_t* b) {
    asm volatile(
        "mma.sync.aligned.m16n8k16.row.col.f32.f16.f16.f32 "
        "{%0,%1,%2,%3}, {%4,%5,%6,%7}, {%8,%9}, {%0,%1,%2,%3};"
        : "+f"(c[0]), "+f"(c[1]), "+f"(c[2]), "+f"(c[3])
        : "r"(a[0]), "r"(a[1]), "r"(a[2]), "r"(a[3]), "r"(b[0]), "r"(b[1]));
}

// ---------------------------------------------------------------------------
// Combined step kernel.
//   z==0: layer1: h1w = tanh(h0r @ Wx1 [+ h1r @ Wh1] + b1)     NST=nst_l1
//         (long jobs first in dispatch order; 0 -> off; 32/64 stages)
//   z==1: layer0: h0w = tanh(h0r @ Wh0 + xw0[inputs[:,t0]])    NST=nst_l0
//         (0 -> epilogue-only: tanh(xw0); <0 -> off)
// ---------------------------------------------------------------------------
__global__ void __launch_bounds__(128, 2)
rnn_pair_kernel(const __half* __restrict__ h0r, __half* __restrict__ h0w,
                const __half* __restrict__ h1r, __half* __restrict__ h1w,
                const __half* __restrict__ Wh0, const __half* __restrict__ Wx1,
                const __half* __restrict__ Wh1,
                const float* __restrict__ b1,
                const __half* __restrict__ xw0,
                const int* __restrict__ inputs, int t0,
                int nst_l0, int nst_l1) {
    const int z = blockIdx.z;
    const int NST = (z == 0) ? nst_l1 : nst_l0;
    if (NST < 0 || (z == 0 && NST == 0)) return;

    extern __shared__ char dsm[];
    const uint32_t tile = (smem_u32(dsm) + 1023u) & ~1023u;

    const int tid = threadIdx.x;
    const int wid = tid >> 5;
    const int lane = tid & 31;
    const int m0 = blockIdx.y * BM;
    const int n0 = blockIdx.x * BN;

    const int mW = (wid & 1) * 64;     // 2 warps along M
    const int nW = (wid >> 1) * 64;    // 2 warps along N

    const __half* Ap[2];
    const __half* Wp[2];
    if (z == 1) { Ap[0] = h0r; Wp[0] = Wh0; Ap[1] = nullptr; Wp[1] = nullptr; }
    else        { Ap[0] = h0r; Wp[0] = Wx1; Ap[1] = h1r;    Wp[1] = Wh1;     }

    // staging: per plane 8KB = 512 x 16B chunks; 4 chunks/thread.
    int lrow[4], lkb[4];
    uint32_t ldst[4];
#pragma unroll
    for (int i = 0; i < 4; ++i) {
        int c = tid + i * 128;
        lrow[i] = c >> 2;
        lkb[i]  = (c & 3) * 16;
        ldst[i] = plane_off(lrow[i], lkb[i]);
    }

    auto load_stage = [&](int s) {
        if (s < NST) {
            const int seg = s >> 5;             // 32 stages per K=1024 segment
            const int k0 = (s & 31) * BK;
            const uint32_t bb = tile + (uint32_t)(s % NBUF) * STAGE;
            const __half* ap = Ap[seg];
            const __half* wp = Wp[seg];
#pragma unroll
            for (int i = 0; i < 4; ++i) {
                size_t ga = (size_t)(m0 + lrow[i]) * U_SZ + k0 + (lkb[i] >> 1);
                size_t gb = (size_t)(n0 + lrow[i]) * U_SZ + k0 + (lkb[i] >> 1);
                cpa16(bb + A_PL + ldst[i], ap + ga);
                cpa16(bb + B_PL + ldst[i], wp + gb);
            }
        }
        asm volatile("cp.async.commit_group;" ::: "memory");   // uniform counting
    };

    float acc[4][8][4];
#pragma unroll
    for (int i = 0; i < 4; ++i)
#pragma unroll
        for (int j = 0; j < 8; ++j)
#pragma unroll
            for (int q = 0; q < 4; ++q) acc[i][j][q] = 0.0f;

    // per-warp LDSM base offsets, computed ONCE (swizzle-XOR identity applies
    // for the ks*32 column advance in the hot loop)
    const int a_row = mW + (lane & 15);
    const int a_cg  = (lane >> 4) * 16;
    const int b_q   = lane >> 3;
    const int b_row = nW + ((b_q >> 1) * 8) + (lane & 7);
    const int b_cg  = (b_q & 1) * 16;

    uint32_t sa[4], sb[4];
#pragma unroll
    for (int i = 0; i < 4; ++i) sa[i] = plane_off(a_row + i * 16, a_cg);
#pragma unroll
    for (int j = 0; j < 4; ++j) sb[j] = plane_off(b_row + j * 16, b_cg);

    // one stage of compute: 2 k16 sub-steps from buffer s%6
    auto compute_stage = [&](int s) {
        const uint32_t bb = tile + (uint32_t)(s % NBUF) * STAGE;
        const uint32_t ba = bb + A_PL;
        const uint32_t bw = bb + B_PL;
#pragma unroll
        for (int ks = 0; ks < 2; ++ks) {
            const uint32_t kx = (uint32_t)(ks * 32);
            uint32_t af[4][4], bf[8][2];
#pragma unroll
            for (int i = 0; i < 4; ++i)
                ldsm4(af[i], ba + (sa[i] ^ kx));
#pragma unroll
            for (int j2 = 0; j2 < 4; ++j2) {
                uint32_t r[4];
                ldsm4(r, bw + (sb[j2] ^ kx));
                bf[j2 * 2][0] = r[0]; bf[j2 * 2][1] = r[1];
                bf[j2 * 2 + 1][0] = r[2]; bf[j2 * 2 + 1][1] = r[3];
            }
#pragma unroll
            for (int i = 0; i < 4; ++i)
#pragma unroll
                for (int j = 0; j < 8; ++j)
                    mma16816(acc[i][j], af[i], bf[j]);
        }
    };

    if (NST > 0) {
        load_stage(0);
        load_stage(1);
        load_stage(2);
        for (int s0 = 0; s0 < NST; s0 += 3) {
            // barrier covers completion of stages s0-3..s0-1 by ALL warps,
            // freeing buffers (s0+3..s0+5)%6 for the loads below.
            __syncthreads();
            load_stage(s0 + 3);
            load_stage(s0 + 4);
            load_stage(s0 + 5);
            asm volatile("cp.async.wait_group 5;" ::: "memory");
            compute_stage(s0);
            if (s0 + 1 < NST) {
                asm volatile("cp.async.wait_group 4;" ::: "memory");
                compute_stage(s0 + 1);
            }
            if (s0 + 2 < NST) {
                asm volatile("cp.async.wait_group 3;" ::: "memory");
                compute_stage(s0 + 2);
            }
        }
    }

    // ---- epilogue ----
    __half* outp = (z == 1) ? h0w : h1w;
    const int gp = lane >> 2;
    const int t4 = lane & 3;
#pragma unroll
    for (int i = 0; i < 4; ++i) {
#pragma unroll
        for (int rh = 0; rh < 2; ++rh) {
            const int m = m0 + mW + i * 16 + gp + rh * 8;
            const __half* xr = nullptr;
            if (z == 1) xr = xw0 + (size_t)inputs[(size_t)m * T_SZ + t0] * U_SZ;
#pragma unroll
            for (int j = 0; j < 8; ++j) {
                const int col = n0 + nW + j * 8 + t4 * 2;
                float v0 = acc[i][j][rh * 2 + 0];
                float v1 = acc[i][j][rh * 2 + 1];
                if (z == 1) {
                    __half2 x2 = *(const __half2*)(xr + col);
                    v0 += __half2float(x2.x); v1 += __half2float(x2.y);
                } else {
                    v0 += b1[col]; v1 += b1[col + 1];
                }
                __half h0 = __float2half_rn(tanhf(v0));
                __half h1 = __float2half_rn(tanhf(v1));
                uint32_t p = (uint32_t)__half_as_ushort(h0) |
                             ((uint32_t)__half_as_ushort(h1) << 16);
                *(uint32_t*)(outp + (size_t)m * U_SZ + col) = p;
            }
        }
    }
}

// ---------------------------------------------------------------------------
// Prep: transpose the three recurrent weight matrices to fp16 [n][k]
// ---------------------------------------------------------------------------
__global__ void __launch_bounds__(256)
transpose_split_kernel(const float* __restrict__ W0, const float* __restrict__ W1,
                       const float* __restrict__ W2) {
    __shared__ float tilebuf[32][33];
    const int z = blockIdx.z;
    const float* W = (z == 0) ? W0 : ((z == 1) ? W1 : W2);
    __half* Th = g_wt[z];
    const int tx = threadIdx.x & 31, ty = threadIdx.x >> 5;
    const int x = blockIdx.x * 32 + tx;
    const int y0 = blockIdx.y * 32;
#pragma unroll
    for (int j = 0; j < 32; j += 8)
        tilebuf[ty + j][tx] = W[(size_t)(y0 + ty + j) * U_SZ + x];
    __syncthreads();
    const int x2 = blockIdx.y * 32 + tx;
#pragma unroll
    for (int j = 0; j < 32; j += 8) {
        int n = blockIdx.x * 32 + ty + j;
        Th[(size_t)n * U_SZ + x2] = __float2half_rn(tilebuf[tx][ty + j]);
    }
}

// ---------------------------------------------------------------------------
// Prep: xw0[v][n] = fp16( b0[n] + sum_k emb[v,k] * Wx0[k,n] )
// ---------------------------------------------------------------------------
__global__ void __launch_bounds__(256)
xw0_kernel(const float* __restrict__ emb, const float* __restrict__ Wx0,
           const float* __restrict__ b0, __half* __restrict__ xw0) {
    __shared__ float es[16][104];
    const int v0 = blockIdx.y * 16;
    const int n = blockIdx.x * 256 + threadIdx.x;
    for (int i = threadIdx.x; i < 16 * E_SZ; i += 256) {
        int r = i / E_SZ, c = i % E_SZ;
        es[r][c] = emb[(size_t)(v0 + r) * E_SZ + c];
    }
    __syncthreads();
    float acc[16];
    float bv = b0[n];
#pragma unroll
    for (int i = 0; i < 16; ++i) acc[i] = bv;
    for (int k = 0; k < E_SZ; ++k) {
        float w = Wx0[(size_t)k * U_SZ + n];
#pragma unroll
        for (int i = 0; i < 16; ++i) acc[i] = fmaf(es[i][k], w, acc[i]);
    }
#pragma unroll
    for (int i = 0; i < 16; ++i)
        xw0[(size_t)(v0 + i) * U_SZ + n] = __float2half_rn(acc[i]);
}

// ---------------------------------------------------------------------------
__global__ void __launch_bounds__(256)
final_kernel(const __half* __restrict__ h1, const float* __restrict__ Wfc,
             const float* __restrict__ bfc, float* __restrict__ out) {
    int warp = (blockIdx.x * blockDim.x + threadIdx.x) >> 5;
    int lane = threadIdx.x & 31;
    if (warp >= B_SZ) return;
    float s = 0.0f;
#pragma unroll
    for (int u = lane; u < U_SZ; u += 32)
        s = fmaf(__half2float(h1[(size_t)warp * U_SZ + u]), Wfc[u], s);
#pragma unroll
    for (int o = 16; o > 0; o >>= 1) s += __shfl_xor_sync(0xffffffffu, s, o);
    if (lane == 0) {
        float z = s + bfc[0];
        out[warp] = 1.0f / (1.0f + expf(-z));
    }
}

// ---------------------------------------------------------------------------
extern "C" void kernel_launch(void* const* d_in, const int* in_sizes, int n_in,
                              void* d_out, int out_size) {
    const int*   inputs = (const int*)  d_in[0];
    const float* emb    = (const float*)d_in[1];
    const float* Wx0    = (const float*)d_in[2];
    const float* Wh0    = (const float*)d_in[3];
    const float* b0     = (const float*)d_in[4];
    const float* Wx1    = (const float*)d_in[5];
    const float* Wh1    = (const float*)d_in[6];
    const float* b1     = (const float*)d_in[7];
    const float* Wfc    = (const float*)d_in[8];
    const float* bfc    = (const float*)d_in[9];
    float* out = (float*)d_out;

    cudaFuncSetAttribute(rnn_pair_kernel,
                         cudaFuncAttributeMaxDynamicSharedMemorySize, SMEM_DYN);

    __half *wt, *h, *xw0;
    cudaGetSymbolAddress((void**)&wt, g_wt);
    cudaGetSymbolAddress((void**)&xw0, g_xw0);
    cudaGetSymbolAddress((void**)&h, g_h);

    const size_t WS = (size_t)U_SZ * U_SZ;
    __half* Wh0q = wt + 0 * WS;
    __half* Wx1q = wt + 1 * WS;
    __half* Wh1q = wt + 2 * WS;

    const size_t HS = (size_t)B_SZ * U_SZ;
    __half* h0[2] = {h + 0 * HS, h + 1 * HS};
    __half* h1[2] = {h + 2 * HS, h + 3 * HS};

    transpose_split_kernel<<<dim3(32, 32, 3), 256>>>(Wh0, Wx1, Wh1);
    xw0_kernel<<<dim3(4, V_SZ / 16), 256>>>(emb, Wx0, b0, xw0);
    // t=0 layer0 is epilogue-only (h0 = tanh(xw0)); t=1 layer1 skips Wh1 seg.

    dim3 grid(U_SZ / BN, B_SZ / BM, 2);   // (8, 32, 2); z=0 = layer1 (long, first)

    // launch t: z=1 computes layer0(t) [t<80]; z=0 computes layer1(t-1) [t>0]
    for (int t = 0; t <= T_SZ; ++t) {
        const int p = t & 1;
        const int nst_l0 = (t < T_SZ) ? ((t == 0) ? 0 : 32) : -1;
        const int nst_l1 = (t > 0) ? ((t == 1) ? 32 : 64) : 0;
        rnn_pair_kernel<<<grid, 128, SMEM_DYN>>>(
            h0[p], h0[p ^ 1],
            h1[p ^ 1], h1[p],
            Wh0q, Wx1q, Wh1q,
            b1, xw0, inputs, t,
            nst_l0, nst_l1);
    }

    // layer1(79) ran at t=80 (p=0), wrote h1[0]
    final_kernel<<<B_SZ / 8, 256>>>(h1[0], Wfc, bfc, out);
}